// round 5
// baseline (speedup 1.0000x reference)
#include <cuda_runtime.h>
#include <cstdint>

#define NPTS    131072
#define H       256
#define M       32          // points per block tile
#define MP      36          // padded row stride (floats): 144B -> 16B aligned rows
#define NLEV    4
#define FEAT    8
#define TMASK   32767u
#define THREADS 256

#define SMEM_FLOATS (2*H*MP + NLEV*FEAT*M + 3*M)
#define SMEM_BYTES  (SMEM_FLOATS * 4)

// ---------- packed f32x2 helpers (sm_103a) ----------
__device__ __forceinline__ unsigned long long pack2(float a, float b) {
    unsigned long long r;
    asm("mov.b64 %0, {%1, %2};" : "=l"(r) : "f"(a), "f"(b));
    return r;
}
__device__ __forceinline__ void unpack2(unsigned long long v, float& a, float& b) {
    asm("mov.b64 {%0, %1}, %2;" : "=f"(a), "=f"(b) : "l"(v));
}
__device__ __forceinline__ unsigned long long ffma2(unsigned long long a,
                                                    unsigned long long b,
                                                    unsigned long long c) {
    unsigned long long d;
    asm("fma.rn.f32x2 %0, %1, %2, %3;" : "=l"(d) : "l"(a), "l"(b), "l"(c));
    return d;
}

// ---------- fast sin: 2-term Cody-Waite reduction + MUFU ----------
// 2pi = 6.2831854820251465 (fp32 hi) + (-1.7484556e-7) (lo)
__device__ __forceinline__ float fast_sin(float x) {
    float k = rintf(x * 0.15915494309189535f);
    float r = fmaf(k, -6.2831854820251465f, x);
    r = fmaf(k, 1.7484556e-7f, r);
    return __sinf(r);   // |r| <= pi: MUFU.SIN abs err ~5e-7
}

// ---------- 256x256 GEMV-batch over the 32-point tile ----------
// shx layout: shx[k*MP + m], acc[q] holds points (2q, 2q+1) packed as f32x2.
__device__ __forceinline__ void gemm_tile(const float* __restrict__ Wg, float bias,
                                          const float* shx,
                                          unsigned long long* acc, int h)
{
    unsigned long long b2 = pack2(bias, bias);
#pragma unroll
    for (int q = 0; q < 16; q++) acc[q] = b2;
#pragma unroll 4
    for (int k = 0; k < H; k++) {
        float w = __ldg(Wg + (k << 8) + h);           // coalesced, L1/L2 hit
        unsigned long long w2 = pack2(w, w);
        const ulonglong2* xr = (const ulonglong2*)(shx + k * MP);  // 16B aligned
#pragma unroll
        for (int q = 0; q < 8; q++) {
            ulonglong2 xv = xr[q];                    // LDS.128 broadcast
            acc[2*q    ] = ffma2(xv.x, w2, acc[2*q    ]);
            acc[2*q + 1] = ffma2(xv.y, w2, acc[2*q + 1]);
        }
    }
}

__global__ void __launch_bounds__(THREADS, 2)
ffb_kernel(const float* __restrict__ in_pos,
           const float* __restrict__ table,
           const float* __restrict__ ffn_A,
           const float* __restrict__ W0,
           const float* __restrict__ b0,
           const float* __restrict__ Ws,
           const float* __restrict__ bs,
           const float* __restrict__ Wh,
           const float* __restrict__ bh,
           float* __restrict__ out)
{
    extern __shared__ float smem[];
    float* bufA  = smem;                       // H*MP floats (activations, transposed)
    float* bufB  = bufA + H * MP;              // H*MP floats
    float* shg   = bufB + H * MP;              // [4 levels * 8 feats][M]
    float* shpos = shg + NLEV * FEAT * M;      // [M][3]

    const int t    = threadIdx.x;              // hidden unit h
    const int base = blockIdx.x * M;

    if (t < 3 * M) shpos[t] = in_pos[base * 3 + t];
    __syncthreads();

    // ---- hash-grid encode: 8 lanes per point, one corner each ----
    {
        const int m = t >> 3;
        const int c = t & 7;
        const unsigned ox = (c >> 2) & 1u, oy = (c >> 1) & 1u, oz = c & 1u;
        // pos01 = (p + BOUND) / (2*BOUND), bit-identical to reference fp32 path
        const float px = (shpos[3*m + 0] + 1.0f) * 0.5f;
        const float py = (shpos[3*m + 1] + 1.0f) * 0.5f;
        const float pz = (shpos[3*m + 2] + 1.0f) * 0.5f;
#pragma unroll
        for (int l = 0; l < NLEV; l++) {
            const float res = (float)(16 << l);
            float sx = px * res, sy = py * res, sz = pz * res;
            float fx = floorf(sx), fy = floorf(sy), fz = floorf(sz);
            float rx = sx - fx, ry = sy - fy, rz = sz - fz;
            unsigned ux = (unsigned)fx + ox;
            unsigned uy = (unsigned)fy + oy;
            unsigned uz = (unsigned)fz + oz;
            unsigned idx = (ux ^ (uy * 2654435761u) ^ (uz * 805459861u)) & TMASK;
            const float4* fp = (const float4*)(table + ((size_t)(l << 15) + idx) * 8);
            float4 f0 = __ldg(fp), f1 = __ldg(fp + 1);
            float w = (ox ? rx : 1.0f - rx) * (oy ? ry : 1.0f - ry) * (oz ? rz : 1.0f - rz);
            float v[8] = { f0.x*w, f0.y*w, f0.z*w, f0.w*w,
                           f1.x*w, f1.y*w, f1.z*w, f1.w*w };
#pragma unroll
            for (int s = 1; s < 8; s <<= 1) {
#pragma unroll
                for (int j = 0; j < 8; j++)
                    v[j] += __shfl_xor_sync(0xffffffffu, v[j], s);
            }
            if (c == 0) {
#pragma unroll
                for (int j = 0; j < 8; j++)
                    shg[(l * FEAT + j) * M + m] = v[j];
            }
        }
    }

    // ---- layer 0: x = sin(pos @ W0 + b0) -> bufA (transposed) ----
    {
        const float wx = W0[t], wy = W0[H + t], wz = W0[2*H + t], bb = b0[t];
#pragma unroll
        for (int m = 0; m < M; m++) {
            float a = fmaf(shpos[3*m + 0], wx,
                      fmaf(shpos[3*m + 1], wy,
                      fmaf(shpos[3*m + 2], wz, bb)));
            bufA[t * MP + m] = fast_sin(a);
        }
    }
    __syncthreads();

    unsigned long long acc[16];
    float outacc[M];
#pragma unroll
    for (int m = 0; m < M; m++) outacc[m] = 0.0f;

#pragma unroll
    for (int l = 0; l < NLEV; l++) {
        const float* xin  = (l & 1) ? bufB : bufA;
        float*       xout = (l & 1) ? bufA : bufB;

        // x @ Ws[l] + bs[l]
        gemm_tile(Ws + l * H * H, bs[l * H + t], xin, acc, t);

        // grid branch: sin(2pi * sigma_l * (g . A_col))
        float Ac[FEAT];
        const float sc = 6.2831853071795864f * (float)(1 << l);
#pragma unroll
        for (int f = 0; f < FEAT; f++)
            Ac[f] = __ldg(ffn_A + ((l * FEAT + f) << 8) + t) * sc;

#pragma unroll
        for (int q = 0; q < 16; q++) {
            float s0, s1;
            unpack2(acc[q], s0, s1);
            const int m0 = 2 * q, m1 = m0 + 1;
            float g0 = 0.0f, g1 = 0.0f;
#pragma unroll
            for (int f = 0; f < FEAT; f++) {
                const float* gp = shg + (l * FEAT + f) * M;
                g0 = fmaf(gp[m0], Ac[f], g0);
                g1 = fmaf(gp[m1], Ac[f], g1);
            }
            float2 xv;
            xv.x = fast_sin(s0) + fast_sin(g0);
            xv.y = fast_sin(s1) + fast_sin(g1);
            *(float2*)(xout + t * MP + m0) = xv;   // st.shared.v2
        }
        __syncthreads();   // xout complete before anyone reads it

        // out += sin(x @ Wh[l] + bh[l])
        gemm_tile(Wh + l * H * H, bh[l * H + t], xout, acc, t);
#pragma unroll
        for (int q = 0; q < 16; q++) {
            float s0, s1;
            unpack2(acc[q], s0, s1);
            outacc[2*q    ] += fast_sin(s0);
            outacc[2*q + 1] += fast_sin(s1);
        }
    }

#pragma unroll
    for (int m = 0; m < M; m++)
        out[(size_t)(base + m) * H + t] = outacc[m];
}

extern "C" void kernel_launch(void* const* d_in, const int* in_sizes, int n_in,
                              void* d_out, int out_size)
{
    const float* in_pos = (const float*)d_in[0];
    const float* table  = (const float*)d_in[1];
    const float* ffn_A  = (const float*)d_in[2];
    const float* W0     = (const float*)d_in[3];
    const float* b0     = (const float*)d_in[4];
    const float* Ws     = (const float*)d_in[5];
    const float* bs     = (const float*)d_in[6];
    const float* Wh     = (const float*)d_in[7];
    const float* bh     = (const float*)d_in[8];
    float* out = (float*)d_out;

    // opt-in to >48KB dynamic smem (idempotent, not a stream op: capture-safe)
    cudaFuncSetAttribute(ffb_kernel, cudaFuncAttributeMaxDynamicSharedMemorySize, SMEM_BYTES);

    ffb_kernel<<<NPTS / M, THREADS, SMEM_BYTES>>>(in_pos, table, ffn_A, W0, b0,
                                                  Ws, bs, Wh, bh, out);
}

// round 7
// speedup vs baseline: 2.5657x; 2.5657x over previous
#include <cuda_runtime.h>
#include <cuda_fp16.h>
#include <cstdint>

#define NPTS    131072
#define MTILE   64
#define NBLK    (NPTS / MTILE)
#define THREADS 256

// ---- smem layout (byte offsets) ----
#define XH_OFF   0          // 64x256 fp16 hi, swizzled [m][k] rows of 512B (32KB)
#define XL_OFF   32768      // lo (32KB)
#define B_OFF    65536      // 4 planes of 32KB: [buf(2)][half(2)][n(256)][k(64)]
#define SHG_OFF  196608     // grid feats [m][32] fp32 (8KB)
#define SHA_OFF  204800     // ffn_A scaled [n][8] fp32 (8KB)
#define SHB_OFF  212992     // biases: [0..255]=bs_l, [256..511]=bh_l (2KB)
#define POS_OFF  215040     // 64x3 fp32 (768B)
#define SMEM_BYTES 215808

// weight scratch: [lm(8)][half(2)][n(256)][k(256)] fp16 = 2MB
__device__ __half g_B[1048576];

// ---------- helpers ----------
__device__ __forceinline__ uint32_t smem_u32(const void* p) {
    uint32_t a;
    asm("{ .reg .u64 t; cvta.to.shared.u64 t, %1; cvt.u32.u64 %0, t; }" : "=r"(a) : "l"(p));
    return a;
}
__device__ __forceinline__ void ldsm4(uint32_t* r, uint32_t addr) {
    asm volatile("ldmatrix.sync.aligned.m8n8.x4.shared.b16 {%0,%1,%2,%3}, [%4];"
        : "=r"(r[0]), "=r"(r[1]), "=r"(r[2]), "=r"(r[3]) : "r"(addr));
}
__device__ __forceinline__ void mma16816(float* c, const uint32_t* a, const uint32_t* b) {
    asm volatile("mma.sync.aligned.m16n8k16.row.col.f32.f16.f16.f32 "
        "{%0,%1,%2,%3}, {%4,%5,%6,%7}, {%8,%9}, {%0,%1,%2,%3};"
        : "+f"(c[0]), "+f"(c[1]), "+f"(c[2]), "+f"(c[3])
        : "r"(a[0]), "r"(a[1]), "r"(a[2]), "r"(a[3]), "r"(b[0]), "r"(b[1]));
}

// fast sin: 2-term Cody-Waite + MUFU (validated R5: rel_err 9e-7)
__device__ __forceinline__ float fast_sin(float x) {
    float k = rintf(x * 0.15915494309189535f);
    float r = fmaf(k, -6.2831854820251465f, x);
    r = fmaf(k, 1.7484556e-7f, r);
    return __sinf(r);
}

// X smem: row m = 512B (256 fp16), 16B chunk c swizzled c^(m&7)
__device__ __forceinline__ void split_store(char* sm, int m, int k, float x) {
    __half hi = __float2half_rn(x);
    __half lo = __float2half_rn(x - __half2float(hi));
    uint32_t c = (uint32_t)(k >> 3);
    uint32_t o = ((uint32_t)m << 9) + ((c ^ (uint32_t)(m & 7)) << 4) + (((uint32_t)k & 7u) << 1);
    *(__half*)(sm + XH_OFF + o) = hi;
    *(__half*)(sm + XL_OFF + o) = lo;
}

// ---------- prep: split+transpose weights to g_B ----------
__global__ void prep_kernel(const float* __restrict__ Ws, const float* __restrict__ Wh) {
    int i = blockIdx.x * blockDim.x + threadIdx.x;
    if (i >= 8 * 65536) return;
    int lm = i >> 16;               // l*2 + mat
    int e  = i & 65535;             // k*256 + n
    int k = e >> 8, n = e & 255;
    const float* W = (lm & 1) ? Wh : Ws;
    float w = W[(lm >> 1) * 65536 + e];
    __half hi = __float2half_rn(w);
    __half lo = __float2half_rn(w - __half2float(hi));
    size_t b = ((size_t)((((lm << 1) + 0) << 8) + n) << 8) + k;
    g_B[b] = hi;
    g_B[b + 65536] = lo;            // half=1 plane
}

// ---------- B chunk loader: gmem -> smem via cp.async (16B) ----------
__device__ __forceinline__ void load_b_chunk(uint32_t sb, int lm, int kc, int buf, int t) {
#pragma unroll
    for (int ii = 0; ii < 16; ii++) {
        int i = t + ii * THREADS;                 // 0..4095
        int half = i >> 11, n = (i >> 3) & 255, cin = i & 7;
        const __half* g = g_B + ((size_t)((((lm << 1) + half) << 8) + n) << 8)
                              + (kc << 6) + (cin << 3);
        uint32_t dst = sb + B_OFF + ((uint32_t)((buf << 1) + half) << 15)
                     + ((uint32_t)n << 7) + ((uint32_t)(cin ^ (n & 7)) << 4);
        asm volatile("cp.async.cg.shared.global [%0], [%1], 16;" :: "r"(dst), "l"(g));
    }
}

// ---------- 3-term split-fp16 GEMM: acc = XhWh + XhWl + XlWh ----------
__device__ __forceinline__ void run_gemm(uint32_t sb, int lm, int t, int lane,
                                         int wm, int wn, float acc[2][8][4])
{
#pragma unroll
    for (int mt = 0; mt < 2; mt++)
#pragma unroll
        for (int nt = 0; nt < 8; nt++)
#pragma unroll
            for (int r = 0; r < 4; r++) acc[mt][nt][r] = 0.0f;

    const int arow = lane & 15;
    const int asel = lane >> 4;
    const int quad = lane >> 3, r8 = lane & 7;
    const int brow_off = ((quad >> 1) << 3) + r8;
    const int bsel = quad & 1;

    load_b_chunk(sb, lm, 0, 0, t);
    asm volatile("cp.async.commit_group;" ::: "memory");

    for (int kc = 0; kc < 4; kc++) {
        asm volatile("cp.async.wait_group 0;" ::: "memory");
        __syncthreads();                          // chunk ready; prev reads done
        if (kc < 3) {
            load_b_chunk(sb, lm, kc + 1, (kc + 1) & 1, t);
            asm volatile("cp.async.commit_group;" ::: "memory");
        }
        const uint32_t bbase = sb + B_OFF + ((uint32_t)((kc & 1) << 1) << 15);
#pragma unroll
        for (int ks = 0; ks < 4; ks++) {
            uint32_t ah[2][4], al[2][4];
            const int cidx = (kc << 3) + (ks << 1) + asel;
#pragma unroll
            for (int mt = 0; mt < 2; mt++) {
                int row = wm * 32 + mt * 16 + arow;
                uint32_t off = ((uint32_t)row << 9) + ((uint32_t)(cidx ^ (row & 7)) << 4);
                ldsm4(ah[mt], sb + XH_OFF + off);
                ldsm4(al[mt], sb + XL_OFF + off);
            }
#pragma unroll
            for (int nt = 0; nt < 4; nt++) {
                uint32_t bh[4], bl[4];
                int row = wn * 64 + nt * 16 + brow_off;
                int cin = (ks << 1) + bsel;
                uint32_t boff = ((uint32_t)row << 7) + ((uint32_t)(cin ^ (row & 7)) << 4);
                ldsm4(bh, bbase + boff);
                ldsm4(bl, bbase + (1u << 15) + boff);
#pragma unroll
                for (int mt = 0; mt < 2; mt++) {
                    mma16816(acc[mt][nt * 2],     ah[mt], bh);
                    mma16816(acc[mt][nt * 2],     ah[mt], bl);
                    mma16816(acc[mt][nt * 2],     al[mt], bh);
                    mma16816(acc[mt][nt * 2 + 1], ah[mt], bh + 2);
                    mma16816(acc[mt][nt * 2 + 1], ah[mt], bl + 2);
                    mma16816(acc[mt][nt * 2 + 1], al[mt], bh + 2);
                }
            }
        }
    }
    __syncthreads();                              // all X/B reads done before epilogue writes
}

// ---------- main ----------
__global__ void __launch_bounds__(THREADS, 1)
ffb_main(const float* __restrict__ in_pos, const float* __restrict__ table,
         const float* __restrict__ ffn_A, const float* __restrict__ W0,
         const float* __restrict__ b0,    const float* __restrict__ bs,
         const float* __restrict__ bh,    float* __restrict__ out)
{
    extern __shared__ char sm[];
    const uint32_t sb = smem_u32(sm);
    const int t = threadIdx.x, w = t >> 5, lane = t & 31;
    const int wm = w & 1, wn = w >> 1;
    const int base = blockIdx.x * MTILE;

    float* shpos = (float*)(sm + POS_OFF);
    float* shg   = (float*)(sm + SHG_OFF);
    float* shA   = (float*)(sm + SHA_OFF);
    float* shb   = (float*)(sm + SHB_OFF);

    if (t < 3 * MTILE) shpos[t] = in_pos[base * 3 + t];
    __syncthreads();

    // ---- hash-grid encode: bit-exact vs reference (validated R5) ----
#pragma unroll
    for (int rep = 0; rep < 2; rep++) {
        int task = t + THREADS * rep;             // 0..511 = 64 pts x 8 corners
        int m = task >> 3, c = task & 7;
        const unsigned ox = (c >> 2) & 1u, oy = (c >> 1) & 1u, oz = c & 1u;
        const float px = (shpos[3*m + 0] + 1.0f) * 0.5f;
        const float py = (shpos[3*m + 1] + 1.0f) * 0.5f;
        const float pz = (shpos[3*m + 2] + 1.0f) * 0.5f;
#pragma unroll
        for (int l = 0; l < 4; l++) {
            const float res = (float)(16 << l);
            float sx = px*res, sy = py*res, sz = pz*res;
            float fx = floorf(sx), fy = floorf(sy), fz = floorf(sz);
            float rx = sx-fx, ry = sy-fy, rz = sz-fz;
            unsigned ux = (unsigned)fx + ox, uy = (unsigned)fy + oy, uz = (unsigned)fz + oz;
            unsigned idx = (ux ^ (uy * 2654435761u) ^ (uz * 805459861u)) & 32767u;
            const float4* fp = (const float4*)(table + ((size_t)(l << 15) + idx) * 8);
            float4 f0 = __ldg(fp), f1 = __ldg(fp + 1);
            float wt = (ox ? rx : 1.0f-rx) * (oy ? ry : 1.0f-ry) * (oz ? rz : 1.0f-rz);
            float v[8] = { f0.x*wt, f0.y*wt, f0.z*wt, f0.w*wt,
                           f1.x*wt, f1.y*wt, f1.z*wt, f1.w*wt };
#pragma unroll
            for (int s = 1; s < 8; s <<= 1)
#pragma unroll
                for (int j = 0; j < 8; j++)
                    v[j] += __shfl_xor_sync(0xffffffffu, v[j], s);
            if (c == 0) {
                float* gp = shg + m * 32 + l * 8;
#pragma unroll
                for (int j = 0; j < 8; j++) gp[j] = v[j];
            }
        }
    }

    // ---- layer 0: X = sin(pos @ W0 + b0), split fp16 hi/lo to smem ----
    {
        const int k = t;                          // 0..255 hidden unit
        const float wx = __ldg(W0 + k), wy = __ldg(W0 + 256 + k),
                    wz = __ldg(W0 + 512 + k), bb = __ldg(b0 + k);
#pragma unroll 8
        for (int m = 0; m < MTILE; m++) {
            float a = fmaf(shpos[3*m], wx, fmaf(shpos[3*m+1], wy, fmaf(shpos[3*m+2], wz, bb)));
            split_store(sm, m, k, fast_sin(a));
        }
    }

    float acc[2][8][4];

#pragma unroll 1
    for (int l = 0; l < 4; l++) {
        __syncthreads();   // guard shA/shb overwrite vs prev layer's epilogue reads
        const float gsc = 6.2831853071795864f * (float)(1 << l);
#pragma unroll
        for (int i = t; i < 2048; i += THREADS) {
            int n = i >> 3, f = i & 7;
            shA[i] = __ldg(ffn_A + ((l * 8 + f) << 8) + n) * gsc;
        }
        shb[t]       = __ldg(bs + (l << 8) + t);
        shb[256 + t] = __ldg(bh + (l << 8) + t);
        // ordered before epilogue reads by run_gemm's internal __syncthreads

        // GEMM1: S = X @ Ws[l]
        run_gemm(sb, l * 2, t, lane, wm, wn, acc);

        // epilogue1: x = sin(S+bs) + sin(grid.A'); split-write new X
#pragma unroll
        for (int mt = 0; mt < 2; mt++) {
#pragma unroll
            for (int h = 0; h < 2; h++) {
                const int m = wm * 32 + mt * 16 + (lane >> 2) + h * 8;
                const float* gp = shg + m * 32 + l * 8;
                float4 g0 = *(const float4*)gp, g1 = *(const float4*)(gp + 4);
#pragma unroll
                for (int nt = 0; nt < 8; nt++) {
                    const int n = wn * 64 + nt * 8 + (lane & 3) * 2;
#pragma unroll
                    for (int u = 0; u < 2; u++) {
                        float S = acc[mt][nt][h * 2 + u] + shb[n + u];
                        const float4 a0 = *(const float4*)(shA + (n + u) * 8);
                        const float4 a1 = *(const float4*)(shA + (n + u) * 8 + 4);
                        float g = g0.x * a0.x;
                        g = fmaf(g0.y, a0.y, g); g = fmaf(g0.z, a0.z, g);
                        g = fmaf(g0.w, a0.w, g); g = fmaf(g1.x, a1.x, g);
                        g = fmaf(g1.y, a1.y, g); g = fmaf(g1.z, a1.z, g);
                        g = fmaf(g1.w, a1.w, g);
                        split_store(sm, m, n + u, fast_sin(S) + fast_sin(g));
                    }
                }
            }
        }
        // GEMM2 reads of X ordered after these writes by its first __syncthreads

        // GEMM2: D = X @ Wh[l]
        run_gemm(sb, l * 2 + 1, t, lane, wm, wn, acc);

        // epilogue2: out[m][n] (+)= sin(D + bh)   (exclusive cell ownership)
#pragma unroll
        for (int mt = 0; mt < 2; mt++) {
#pragma unroll
            for (int h = 0; h < 2; h++) {
                const int m = wm * 32 + mt * 16 + (lane >> 2) + h * 8;
                float* op = out + (size_t)(base + m) * 256;
#pragma unroll
                for (int nt = 0; nt < 8; nt++) {
                    const int n = wn * 64 + nt * 8 + (lane & 3) * 2;
                    float v0 = fast_sin(acc[mt][nt][h * 2 + 0] + shb[256 + n]);
                    float v1 = fast_sin(acc[mt][nt][h * 2 + 1] + shb[256 + n + 1]);
                    float2* p = (float2*)(op + n);
                    if (l == 0) {
                        *p = make_float2(v0, v1);
                    } else {
                        float2 o = *p;
                        *p = make_float2(o.x + v0, o.y + v1);
                    }
                }
            }
        }
    }
}

extern "C" void kernel_launch(void* const* d_in, const int* in_sizes, int n_in,
                              void* d_out, int out_size)
{
    const float* in_pos = (const float*)d_in[0];
    const float* table  = (const float*)d_in[1];
    const float* ffn_A  = (const float*)d_in[2];
    const float* W0     = (const float*)d_in[3];
    const float* b0     = (const float*)d_in[4];
    const float* Ws     = (const float*)d_in[5];
    const float* bs     = (const float*)d_in[6];
    const float* Wh     = (const float*)d_in[7];
    const float* bh     = (const float*)d_in[8];
    float* out = (float*)d_out;

    cudaFuncSetAttribute(ffb_main, cudaFuncAttributeMaxDynamicSharedMemorySize, SMEM_BYTES);

    prep_kernel<<<(8 * 65536 + 255) / 256, 256>>>(Ws, Wh);
    ffb_main<<<NBLK, THREADS, SMEM_BYTES>>>(in_pos, table, ffn_A, W0, b0, bs, bh, out);
}

// round 10
// speedup vs baseline: 3.6344x; 1.4165x over previous
#include <cuda_runtime.h>
#include <cuda_fp16.h>
#include <cstdint>

#define NPTS    131072
#define MTILE   32
#define NBLK    (NPTS / MTILE)
#define THREADS 256

// ---- smem layout (byte offsets) ----
#define XH_OFF   0          // 32x256 fp16 hi, swizzled rows of 512B (16KB)
#define XL_OFF   16384      // lo (16KB)
#define B_OFF    32768      // 2 bufs x [n(256)][k(64)] fp16 = 2x32KB
#define SHG_OFF  98304      // grid feats [m][32] fp32 (4KB)
#define SHA_OFF  102400     // ffn_A scaled [n][8] fp32 (8KB)
#define SHB_OFF  110592     // biases: [0..255]=bs_l, [256..511]=bh_l (2KB)
#define POS_OFF  112640     // 32x3 fp32 (384B)
#define SMEM_BYTES 113024

// weight scratch: [lm(8)][n(256)][k(256)] fp16 = 1MB
__device__ __half g_B[524288];

// ---------- helpers ----------
__device__ __forceinline__ uint32_t smem_u32(const void* p) {
    uint32_t a;
    asm("{ .reg .u64 t; cvta.to.shared.u64 t, %1; cvt.u32.u64 %0, t; }" : "=r"(a) : "l"(p));
    return a;
}
__device__ __forceinline__ void ldsm4(uint32_t* r, uint32_t addr) {
    asm volatile("ldmatrix.sync.aligned.m8n8.x4.shared.b16 {%0,%1,%2,%3}, [%4];"
        : "=r"(r[0]), "=r"(r[1]), "=r"(r[2]), "=r"(r[3]) : "r"(addr));
}
__device__ __forceinline__ void mma16816(float* c, const uint32_t* a, const uint32_t* b) {
    asm volatile("mma.sync.aligned.m16n8k16.row.col.f32.f16.f16.f32 "
        "{%0,%1,%2,%3}, {%4,%5,%6,%7}, {%8,%9}, {%0,%1,%2,%3};"
        : "+f"(c[0]), "+f"(c[1]), "+f"(c[2]), "+f"(c[3])
        : "r"(a[0]), "r"(a[1]), "r"(a[2]), "r"(a[3]), "r"(b[0]), "r"(b[1]));
}

// fast sin: 2-term Cody-Waite + MUFU (validated R5: rel_err 9e-7)
__device__ __forceinline__ float fast_sin(float x) {
    float k = rintf(x * 0.15915494309189535f);
    float r = fmaf(k, -6.2831854820251465f, x);
    r = fmaf(k, 1.7484556e-7f, r);
    return __sinf(r);
}

// X smem: row m = 512B (256 fp16), 16B chunk c swizzled c^(m&7)
__device__ __forceinline__ void split_store(char* sm, int m, int k, float x) {
    __half hi = __float2half_rn(x);
    __half lo = __float2half_rn(x - __half2float(hi));
    uint32_t c = (uint32_t)(k >> 3);
    uint32_t o = ((uint32_t)m << 9) + ((c ^ (uint32_t)(m & 7)) << 4) + (((uint32_t)k & 7u) << 1);
    *(__half*)(sm + XH_OFF + o) = hi;
    *(__half*)(sm + XL_OFF + o) = lo;
}

// ---------- prep: fp16-round + transpose weights to g_B[lm][n][k] ----------
__global__ void prep_kernel(const float* __restrict__ Ws, const float* __restrict__ Wh) {
    int i = blockIdx.x * blockDim.x + threadIdx.x;
    if (i >= 8 * 65536) return;
    int lm = i >> 16;               // l*2 + mat
    int e  = i & 65535;             // k*256 + n
    int k = e >> 8, n = e & 255;
    const float* W = (lm & 1) ? Wh : Ws;
    g_B[(lm << 16) + (n << 8) + k] = __float2half_rn(W[(lm >> 1) * 65536 + e]);
}

// ---------- B chunk loader: gmem -> smem via cp.async (16B) ----------
__device__ __forceinline__ void load_b_chunk(uint32_t sb, int lm, int kc, int buf, int t) {
#pragma unroll
    for (int ii = 0; ii < 8; ii++) {
        int i = t + ii * THREADS;                 // 0..2047
        int n = i >> 3, cin = i & 7;
        const __half* g = g_B + (lm << 16) + (n << 8) + (kc << 6) + (cin << 3);
        uint32_t dst = sb + B_OFF + ((uint32_t)buf << 15)
                     + ((uint32_t)n << 7) + ((uint32_t)(cin ^ (n & 7)) << 4);
        asm volatile("cp.async.cg.shared.global [%0], [%1], 16;" :: "r"(dst), "l"(g));
    }
}

// ---------- 2-pass split GEMM: acc = (Xh + Xl) @ W,  K=256 in 4 chunks ----------
__device__ __forceinline__ void run_gemm(uint32_t sb, int lm, int t, int lane,
                                         int wn, float acc[2][4][4])
{
#pragma unroll
    for (int mt = 0; mt < 2; mt++)
#pragma unroll
        for (int nt = 0; nt < 4; nt++)
#pragma unroll
            for (int r = 0; r < 4; r++) acc[mt][nt][r] = 0.0f;

    const int arow = lane & 15;
    const int asel = lane >> 4;
    const int quad = lane >> 3, r8 = lane & 7;
    const int brow_off = ((quad >> 1) << 3) + r8;
    const int bsel = quad & 1;

    load_b_chunk(sb, lm, 0, 0, t);
    asm volatile("cp.async.commit_group;" ::: "memory");

    for (int kc = 0; kc < 4; kc++) {
        asm volatile("cp.async.wait_group 0;" ::: "memory");
        __syncthreads();                          // chunk ready; prev reads done
        if (kc < 3) {
            load_b_chunk(sb, lm, kc + 1, (kc + 1) & 1, t);
            asm volatile("cp.async.commit_group;" ::: "memory");
        }
        const uint32_t bbase = sb + B_OFF + ((uint32_t)(kc & 1) << 15);
#pragma unroll
        for (int ks = 0; ks < 4; ks++) {
            uint32_t ah[2][4], al[2][4];
            const int cidx = (kc << 3) + (ks << 1) + asel;
#pragma unroll
            for (int mt = 0; mt < 2; mt++) {
                int row = mt * 16 + arow;
                uint32_t off = ((uint32_t)row << 9) + ((uint32_t)(cidx ^ (row & 7)) << 4);
                ldsm4(ah[mt], sb + XH_OFF + off);
                ldsm4(al[mt], sb + XL_OFF + off);
            }
#pragma unroll
            for (int nt = 0; nt < 2; nt++) {
                uint32_t bh[4];
                int row = wn * 32 + nt * 16 + brow_off;
                int cin = (ks << 1) + bsel;
                uint32_t boff = ((uint32_t)row << 7) + ((uint32_t)(cin ^ (row & 7)) << 4);
                ldsm4(bh, bbase + boff);
#pragma unroll
                for (int mt = 0; mt < 2; mt++) {
                    mma16816(acc[mt][nt * 2],     ah[mt], bh);
                    mma16816(acc[mt][nt * 2],     al[mt], bh);
                    mma16816(acc[mt][nt * 2 + 1], ah[mt], bh + 2);
                    mma16816(acc[mt][nt * 2 + 1], al[mt], bh + 2);
                }
            }
        }
    }
    __syncthreads();                              // all X/B reads done before epilogue writes
}

// ---------- main ----------
__global__ void __launch_bounds__(THREADS, 2)
ffb_main(const float* __restrict__ in_pos, const float* __restrict__ table,
         const float* __restrict__ ffn_A, const float* __restrict__ W0,
         const float* __restrict__ b0,    const float* __restrict__ bs,
         const float* __restrict__ bh,    float* __restrict__ out)
{
    extern __shared__ char sm[];
    const uint32_t sb = smem_u32(sm);
    const int t = threadIdx.x, w = t >> 5, lane = t & 31;
    const int wn = w;                              // warp owns 32-col span
    const int base = blockIdx.x * MTILE;

    float* shpos = (float*)(sm + POS_OFF);
    float* shg   = (float*)(sm + SHG_OFF);
    float* shA   = (float*)(sm + SHA_OFF);
    float* shb   = (float*)(sm + SHB_OFF);

    if (t < 3 * MTILE) shpos[t] = in_pos[base * 3 + t];
    __syncthreads();

    // ---- hash-grid encode: 256 tasks = 32 pts x 8 corners (bit-exact, validated) ----
    {
        int m = t >> 3, c = t & 7;
        const unsigned ox = (c >> 2) & 1u, oy = (c >> 1) & 1u, oz = c & 1u;
        const float px = (shpos[3*m + 0] + 1.0f) * 0.5f;
        const float py = (shpos[3*m + 1] + 1.0f) * 0.5f;
        const float pz = (shpos[3*m + 2] + 1.0f) * 0.5f;
#pragma unroll
        for (int l = 0; l < 4; l++) {
            const float res = (float)(16 << l);
            float sx = px*res, sy = py*res, sz = pz*res;
            float fx = floorf(sx), fy = floorf(sy), fz = floorf(sz);
            float rx = sx-fx, ry = sy-fy, rz = sz-fz;
            unsigned ux = (unsigned)fx + ox, uy = (unsigned)fy + oy, uz = (unsigned)fz + oz;
            unsigned idx = (ux ^ (uy * 2654435761u) ^ (uz * 805459861u)) & 32767u;
            const float4* fp = (const float4*)(table + ((size_t)(l << 15) + idx) * 8);
            float4 f0 = __ldg(fp), f1 = __ldg(fp + 1);
            float wt = (ox ? rx : 1.0f-rx) * (oy ? ry : 1.0f-ry) * (oz ? rz : 1.0f-rz);
            float v[8] = { f0.x*wt, f0.y*wt, f0.z*wt, f0.w*wt,
                           f1.x*wt, f1.y*wt, f1.z*wt, f1.w*wt };
#pragma unroll
            for (int s = 1; s < 8; s <<= 1)
#pragma unroll
                for (int j = 0; j < 8; j++)
                    v[j] += __shfl_xor_sync(0xffffffffu, v[j], s);
            if (c == 0) {
                float* gp = shg + m * 32 + l * 8;
#pragma unroll
                for (int j = 0; j < 8; j++) gp[j] = v[j];
            }
        }
    }

    // ---- layer 0: X = sin(pos @ W0 + b0), split fp16 hi/lo to smem ----
    {
        const int k = t;
        const float wx = __ldg(W0 + k), wy = __ldg(W0 + 256 + k),
                    wz = __ldg(W0 + 512 + k), bb = __ldg(b0 + k);
#pragma unroll 8
        for (int m = 0; m < MTILE; m++) {
            float a = fmaf(shpos[3*m], wx, fmaf(shpos[3*m+1], wy, fmaf(shpos[3*m+2], wz, bb)));
            split_store(sm, m, k, fast_sin(a));
        }
    }

    float acc[2][4][4];

#pragma unroll 1
    for (int l = 0; l < 4; l++) {
        __syncthreads();   // guard shA/shb overwrite vs prev layer's epilogue reads
        const float gsc = 6.2831853071795864f * (float)(1 << l);
#pragma unroll
        for (int i = t; i < 2048; i += THREADS) {
            int n = i >> 3, f = i & 7;
            shA[i] = __ldg(ffn_A + ((l * 8 + f) << 8) + n) * gsc;
        }
        shb[t]       = __ldg(bs + (l << 8) + t);
        shb[256 + t] = __ldg(bh + (l << 8) + t);
        // ordered before epilogue reads by run_gemm's internal __syncthreads

        // GEMM1: S = X @ Ws[l]
        run_gemm(sb, l * 2, t, lane, wn, acc);

        // epilogue1: x = sin(S+bs) + sin(grid.A'); split-write new X
#pragma unroll
        for (int mt = 0; mt < 2; mt++) {
#pragma unroll
            for (int h = 0; h < 2; h++) {
                const int m = mt * 16 + (lane >> 2) + h * 8;
                const float* gp = shg + m * 32 + l * 8;
                float4 g0 = *(const float4*)gp, g1 = *(const float4*)(gp + 4);
#pragma unroll
                for (int nt = 0; nt < 4; nt++) {
                    const int n = wn * 32 + nt * 8 + (lane & 3) * 2;
#pragma unroll
                    for (int u = 0; u < 2; u++) {
                        float S = acc[mt][nt][h * 2 + u] + shb[n + u];
                        const float4 a0 = *(const float4*)(shA + (n + u) * 8);
                        const float4 a1 = *(const float4*)(shA + (n + u) * 8 + 4);
                        float g = g0.x * a0.x;
                        g = fmaf(g0.y, a0.y, g); g = fmaf(g0.z, a0.z, g);
                        g = fmaf(g0.w, a0.w, g); g = fmaf(g1.x, a1.x, g);
                        g = fmaf(g1.y, a1.y, g); g = fmaf(g1.z, a1.z, g);
                        g = fmaf(g1.w, a1.w, g);
                        split_store(sm, m, n + u, fast_sin(S) + fast_sin(g));
                    }
                }
            }
        }
        // GEMM2 reads of X ordered after these writes by its first __syncthreads

        // GEMM2: D = X @ Wh[l]
        run_gemm(sb, l * 2 + 1, t, lane, wn, acc);

        // epilogue2: out[m][n] (+)= sin(D + bh)   (exclusive cell ownership)
#pragma unroll
        for (int mt = 0; mt < 2; mt++) {
#pragma unroll
            for (int h = 0; h < 2; h++) {
                const int m = mt * 16 + (lane >> 2) + h * 8;
                float* op = out + (size_t)(base + m) * 256;
#pragma unroll
                for (int nt = 0; nt < 4; nt++) {
                    const int n = wn * 32 + nt * 8 + (lane & 3) * 2;
                    float v0 = fast_sin(acc[mt][nt][h * 2 + 0] + shb[256 + n]);
                    float v1 = fast_sin(acc[mt][nt][h * 2 + 1] + shb[256 + n + 1]);
                    float2* p = (float2*)(op + n);
                    if (l == 0) {
                        *p = make_float2(v0, v1);
                    } else {
                        float2 o = *p;
                        *p = make_float2(o.x + v0, o.y + v1);
                    }
                }
            }
        }
    }
}

extern "C" void kernel_launch(void* const* d_in, const int* in_sizes, int n_in,
                              void* d_out, int out_size)
{
    const float* in_pos = (const float*)d_in[0];
    const float* table  = (const float*)d_in[1];
    const float* ffn_A  = (const float*)d_in[2];
    const float* W0     = (const float*)d_in[3];
    const float* b0     = (const float*)d_in[4];
    const float* Ws     = (const float*)d_in[5];
    const float* bs     = (const float*)d_in[6];
    const float* Wh     = (const float*)d_in[7];
    const float* bh     = (const float*)d_in[8];
    float* out = (float*)d_out;

    cudaFuncSetAttribute(ffb_main, cudaFuncAttributeMaxDynamicSharedMemorySize, SMEM_BYTES);

    prep_kernel<<<(8 * 65536 + 255) / 256, 256>>>(Ws, Wh);
    ffb_main<<<NBLK, THREADS, SMEM_BYTES>>>(in_pos, table, ffn_A, W0, b0, bs, bh, out);
}

// round 12
// speedup vs baseline: 4.6632x; 1.2831x over previous
#include <cuda_runtime.h>
#include <cuda_fp16.h>
#include <cstdint>

#define NPTS    131072
#define MTILE   32
#define NBLK    (NPTS / MTILE)
#define THREADS 256

// ---- smem layout (byte offsets) ----
#define XH_OFF   0          // 32x256 fp16, swizzled rows of 512B (16KB)
#define B_OFF    16384      // 2 bufs x [n(256)][k(64)] fp16 = 2x32KB
#define SHG_OFF  81920      // grid feats [m][32] fp32 (4KB)
#define SHA_OFF  86016      // ffn_A scaled [n][8] fp32 (8KB)
#define SHB_OFF  94208      // biases: [0..255]=bs_l, [256..511]=bh_l (2KB)
#define POS_OFF  96256      // 32x3 fp32 (384B)
#define SMEM_BYTES 96640

// weight scratch: [lm(8)][n(256)][k(256)] fp16 = 1MB
__device__ __half g_B[524288];

// ---------- helpers ----------
__device__ __forceinline__ uint32_t smem_u32(const void* p) {
    uint32_t a;
    asm("{ .reg .u64 t; cvta.to.shared.u64 t, %1; cvt.u32.u64 %0, t; }" : "=r"(a) : "l"(p));
    return a;
}
__device__ __forceinline__ void ldsm4(uint32_t* r, uint32_t addr) {
    asm volatile("ldmatrix.sync.aligned.m8n8.x4.shared.b16 {%0,%1,%2,%3}, [%4];"
        : "=r"(r[0]), "=r"(r[1]), "=r"(r[2]), "=r"(r[3]) : "r"(addr));
}
__device__ __forceinline__ void mma16816(float* c, const uint32_t* a, const uint32_t* b) {
    asm volatile("mma.sync.aligned.m16n8k16.row.col.f32.f16.f16.f32 "
        "{%0,%1,%2,%3}, {%4,%5,%6,%7}, {%8,%9}, {%0,%1,%2,%3};"
        : "+f"(c[0]), "+f"(c[1]), "+f"(c[2]), "+f"(c[3])
        : "r"(a[0]), "r"(a[1]), "r"(a[2]), "r"(a[3]), "r"(b[0]), "r"(b[1]));
}

// fast sin: 2-term Cody-Waite + MUFU (validated R5: rel_err 9e-7)
__device__ __forceinline__ float fast_sin(float x) {
    float k = rintf(x * 0.15915494309189535f);
    float r = fmaf(k, -6.2831854820251465f, x);
    r = fmaf(k, 1.7484556e-7f, r);
    return __sinf(r);
}

// X smem: row m = 512B (256 fp16), 16B chunk c swizzled c^(m&7)
__device__ __forceinline__ void store_x(char* sm, int m, int k, float x) {
    uint32_t c = (uint32_t)(k >> 3);
    uint32_t o = ((uint32_t)m << 9) + ((c ^ (uint32_t)(m & 7)) << 4) + (((uint32_t)k & 7u) << 1);
    *(__half*)(sm + XH_OFF + o) = __float2half_rn(x);
}

// ---------- prep: fp16-round + transpose weights to g_B[lm][n][k] ----------
__global__ void prep_kernel(const float* __restrict__ Ws, const float* __restrict__ Wh) {
    int i = blockIdx.x * blockDim.x + threadIdx.x;
    if (i >= 8 * 65536) return;
    int lm = i >> 16;               // l*2 + mat
    int e  = i & 65535;             // k*256 + n
    int k = e >> 8, n = e & 255;
    const float* W = (lm & 1) ? Wh : Ws;
    g_B[(lm << 16) + (n << 8) + k] = __float2half_rn(W[(lm >> 1) * 65536 + e]);
}

// ---------- B chunk loader: gmem -> smem via cp.async (16B) ----------
__device__ __forceinline__ void load_b_chunk(uint32_t sb, int lm, int kc, int buf, int t) {
#pragma unroll
    for (int ii = 0; ii < 8; ii++) {
        int i = t + ii * THREADS;                 // 0..2047
        int n = i >> 3, cin = i & 7;
        const __half* g = g_B + (lm << 16) + (n << 8) + (kc << 6) + (cin << 3);
        uint32_t dst = sb + B_OFF + ((uint32_t)buf << 15)
                     + ((uint32_t)n << 7) + ((uint32_t)(cin ^ (n & 7)) << 4);
        asm volatile("cp.async.cg.shared.global [%0], [%1], 16;" :: "r"(dst), "l"(g));
    }
}

// ---------- single-pass fp16 GEMM: acc = X @ W,  K=256 in 4 chunks ----------
__device__ __forceinline__ void run_gemm(uint32_t sb, int lm, int t, int lane,
                                         int wn, float acc[2][4][4])
{
#pragma unroll
    for (int mt = 0; mt < 2; mt++)
#pragma unroll
        for (int nt = 0; nt < 4; nt++)
#pragma unroll
            for (int r = 0; r < 4; r++) acc[mt][nt][r] = 0.0f;

    const int arow = lane & 15;
    const int asel = lane >> 4;
    const int quad = lane >> 3, r8 = lane & 7;
    const int brow_off = ((quad >> 1) << 3) + r8;
    const int bsel = quad & 1;

    load_b_chunk(sb, lm, 0, 0, t);
    asm volatile("cp.async.commit_group;" ::: "memory");

    for (int kc = 0; kc < 4; kc++) {
        asm volatile("cp.async.wait_group 0;" ::: "memory");
        __syncthreads();                          // chunk ready; prev reads done
        if (kc < 3) {
            load_b_chunk(sb, lm, kc + 1, (kc + 1) & 1, t);
            asm volatile("cp.async.commit_group;" ::: "memory");
        }
        const uint32_t bbase = sb + B_OFF + ((uint32_t)(kc & 1) << 15);
#pragma unroll
        for (int ks = 0; ks < 4; ks++) {
            uint32_t ah[2][4];
            const int cidx = (kc << 3) + (ks << 1) + asel;
#pragma unroll
            for (int mt = 0; mt < 2; mt++) {
                int row = mt * 16 + arow;
                uint32_t off = ((uint32_t)row << 9) + ((uint32_t)(cidx ^ (row & 7)) << 4);
                ldsm4(ah[mt], sb + XH_OFF + off);
            }
#pragma unroll
            for (int nt = 0; nt < 2; nt++) {
                uint32_t bh[4];
                int row = wn * 32 + nt * 16 + brow_off;
                int cin = (ks << 1) + bsel;
                uint32_t boff = ((uint32_t)row << 7) + ((uint32_t)(cin ^ (row & 7)) << 4);
                ldsm4(bh, bbase + boff);
#pragma unroll
                for (int mt = 0; mt < 2; mt++) {
                    mma16816(acc[mt][nt * 2],     ah[mt], bh);
                    mma16816(acc[mt][nt * 2 + 1], ah[mt], bh + 2);
                }
            }
        }
    }
    __syncthreads();                              // all X/B reads done before epilogue writes
}

// ---------- main ----------
__global__ void __launch_bounds__(THREADS, 2)
ffb_main(const float* __restrict__ in_pos, const float* __restrict__ table,
         const float* __restrict__ ffn_A, const float* __restrict__ W0,
         const float* __restrict__ b0,    const float* __restrict__ bs,
         const float* __restrict__ bh,    float* __restrict__ out)
{
    extern __shared__ char sm[];
    const uint32_t sb = smem_u32(sm);
    const int t = threadIdx.x, w = t >> 5, lane = t & 31;
    const int wn = w;                              // warp owns 32-col span
    const int base = blockIdx.x * MTILE;

    float* shpos = (float*)(sm + POS_OFF);
    float* shg   = (float*)(sm + SHG_OFF);
    float* shA   = (float*)(sm + SHA_OFF);
    float* shb   = (float*)(sm + SHB_OFF);

    if (t < 3 * MTILE) shpos[t] = in_pos[base * 3 + t];
    __syncthreads();

    // ---- hash-grid encode: 256 tasks = 32 pts x 8 corners (bit-exact, validated) ----
    {
        int m = t >> 3, c = t & 7;
        const unsigned ox = (c >> 2) & 1u, oy = (c >> 1) & 1u, oz = c & 1u;
        const float px = (shpos[3*m + 0] + 1.0f) * 0.5f;
        const float py = (shpos[3*m + 1] + 1.0f) * 0.5f;
        const float pz = (shpos[3*m + 2] + 1.0f) * 0.5f;
#pragma unroll
        for (int l = 0; l < 4; l++) {
            const float res = (float)(16 << l);
            float sx = px*res, sy = py*res, sz = pz*res;
            float fx = floorf(sx), fy = floorf(sy), fz = floorf(sz);
            float rx = sx-fx, ry = sy-fy, rz = sz-fz;
            unsigned ux = (unsigned)fx + ox, uy = (unsigned)fy + oy, uz = (unsigned)fz + oz;
            unsigned idx = (ux ^ (uy * 2654435761u) ^ (uz * 805459861u)) & 32767u;
            const float4* fp = (const float4*)(table + ((size_t)(l << 15) + idx) * 8);
            float4 f0 = __ldg(fp), f1 = __ldg(fp + 1);
            float wt = (ox ? rx : 1.0f-rx) * (oy ? ry : 1.0f-ry) * (oz ? rz : 1.0f-rz);
            float v[8] = { f0.x*wt, f0.y*wt, f0.z*wt, f0.w*wt,
                           f1.x*wt, f1.y*wt, f1.z*wt, f1.w*wt };
#pragma unroll
            for (int s = 1; s < 8; s <<= 1)
#pragma unroll
                for (int j = 0; j < 8; j++)
                    v[j] += __shfl_xor_sync(0xffffffffu, v[j], s);
            if (c == 0) {
                float* gp = shg + m * 32 + l * 8;
#pragma unroll
                for (int j = 0; j < 8; j++) gp[j] = v[j];
            }
        }
    }

    // ---- layer 0: X = sin(pos @ W0 + b0) -> fp16 smem ----
    {
        const int k = t;
        const float wx = __ldg(W0 + k), wy = __ldg(W0 + 256 + k),
                    wz = __ldg(W0 + 512 + k), bb = __ldg(b0 + k);
#pragma unroll 8
        for (int m = 0; m < MTILE; m++) {
            float a = fmaf(shpos[3*m], wx, fmaf(shpos[3*m+1], wy, fmaf(shpos[3*m+2], wz, bb)));
            store_x(sm, m, k, fast_sin(a));
        }
    }

    float acc[2][4][4];

#pragma unroll 1
    for (int l = 0; l < 4; l++) {
        __syncthreads();   // guard shA/shb overwrite vs prev layer's epilogue reads
        const float gsc = 6.2831853071795864f * (float)(1 << l);
#pragma unroll
        for (int i = t; i < 2048; i += THREADS) {
            int n = i >> 3, f = i & 7;
            shA[i] = __ldg(ffn_A + ((l * 8 + f) << 8) + n) * gsc;
        }
        shb[t]       = __ldg(bs + (l << 8) + t);
        shb[256 + t] = __ldg(bh + (l << 8) + t);
        // ordered before epilogue reads by run_gemm's internal __syncthreads

        // GEMM1: S = X @ Ws[l]
        run_gemm(sb, l * 2, t, lane, wn, acc);

        // epilogue1: x = sin(S+bs) + sin(grid.A'); write new X (fp16)
#pragma unroll
        for (int mt = 0; mt < 2; mt++) {
#pragma unroll
            for (int h = 0; h < 2; h++) {
                const int m = mt * 16 + (lane >> 2) + h * 8;
                const float* gp = shg + m * 32 + l * 8;
                float4 g0 = *(const float4*)gp, g1 = *(const float4*)(gp + 4);
#pragma unroll
                for (int nt = 0; nt < 4; nt++) {
                    const int n = wn * 32 + nt * 8 + (lane & 3) * 2;
#pragma unroll
                    for (int u = 0; u < 2; u++) {
                        float S = acc[mt][nt][h * 2 + u] + shb[n + u];
                        const float4 a0 = *(const float4*)(shA + (n + u) * 8);
                        const float4 a1 = *(const float4*)(shA + (n + u) * 8 + 4);
                        float g = g0.x * a0.x;
                        g = fmaf(g0.y, a0.y, g); g = fmaf(g0.z, a0.z, g);
                        g = fmaf(g0.w, a0.w, g); g = fmaf(g1.x, a1.x, g);
                        g = fmaf(g1.y, a1.y, g); g = fmaf(g1.z, a1.z, g);
                        g = fmaf(g1.w, a1.w, g);
                        store_x(sm, m, n + u, fast_sin(S) + fast_sin(g));
                    }
                }
            }
        }
        // GEMM2 reads of X ordered after these writes by its first __syncthreads

        // GEMM2: D = X @ Wh[l]
        run_gemm(sb, l * 2 + 1, t, lane, wn, acc);

        // epilogue2: out[m][n] (+)= sin(D + bh)   (exclusive cell ownership)
#pragma unroll
        for (int mt = 0; mt < 2; mt++) {
#pragma unroll
            for (int h = 0; h < 2; h++) {
                const int m = mt * 16 + (lane >> 2) + h * 8;
                float* op = out + (size_t)(base + m) * 256;
#pragma unroll
                for (int nt = 0; nt < 4; nt++) {
                    const int n = wn * 32 + nt * 8 + (lane & 3) * 2;
                    float v0 = fast_sin(acc[mt][nt][h * 2 + 0] + shb[256 + n]);
                    float v1 = fast_sin(acc[mt][nt][h * 2 + 1] + shb[256 + n + 1]);
                    float2* p = (float2*)(op + n);
                    if (l == 0) {
                        *p = make_float2(v0, v1);
                    } else {
                        float2 o = *p;
                        *p = make_float2(o.x + v0, o.y + v1);
                    }
                }
            }
        }
    }
}

extern "C" void kernel_launch(void* const* d_in, const int* in_sizes, int n_in,
                              void* d_out, int out_size)
{
    const float* in_pos = (const float*)d_in[0];
    const float* table  = (const float*)d_in[1];
    const float* ffn_A  = (const float*)d_in[2];
    const float* W0     = (const float*)d_in[3];
    const float* b0     = (const float*)d_in[4];
    const float* Ws     = (const float*)d_in[5];
    const float* bs     = (const float*)d_in[6];
    const float* Wh     = (const float*)d_in[7];
    const float* bh     = (const float*)d_in[8];
    float* out = (float*)d_out;

    cudaFuncSetAttribute(ffb_main, cudaFuncAttributeMaxDynamicSharedMemorySize, SMEM_BYTES);

    prep_kernel<<<(8 * 65536 + 255) / 256, 256>>>(Ws, Wh);
    ffb_main<<<NBLK, THREADS, SMEM_BYTES>>>(in_pos, table, ffn_A, W0, b0, bs, bh, out);
}

// round 13
// speedup vs baseline: 4.9309x; 1.0574x over previous
#include <cuda_runtime.h>
#include <cuda_fp16.h>
#include <cstdint>

#define NPTS    131072
#define MTILE   64
#define NBLK    (NPTS / MTILE)
#define THREADS 256

// ---- smem layout (byte offsets) ----
#define X_OFF    0          // 64x256 fp16, swizzled rows of 512B (32KB)
#define B_OFF    32768      // 2 bufs x [n(256)][k(32)] fp16 = 2x16KB
#define SHG_OFF  65536      // grid feats [m][32] fp32 (8KB)
#define SHA_OFF  73728      // ffn_A scaled [n][8] fp32 (8KB)
#define SHB_OFF  81920      // biases: [0..255]=bs_l, [256..511]=bh_l (2KB)
#define POS_OFF  83968      // 64x3 fp32 (768B)
#define SMEM_BYTES 84736

// weight scratch: [lm(8)][n(256)][k(256)] fp16 = 1MB
__device__ __half g_B[524288];

// ---------- helpers ----------
__device__ __forceinline__ uint32_t smem_u32(const void* p) {
    uint32_t a;
    asm("{ .reg .u64 t; cvta.to.shared.u64 t, %1; cvt.u32.u64 %0, t; }" : "=r"(a) : "l"(p));
    return a;
}
__device__ __forceinline__ void ldsm4(uint32_t* r, uint32_t addr) {
    asm volatile("ldmatrix.sync.aligned.m8n8.x4.shared.b16 {%0,%1,%2,%3}, [%4];"
        : "=r"(r[0]), "=r"(r[1]), "=r"(r[2]), "=r"(r[3]) : "r"(addr));
}
__device__ __forceinline__ void mma16816(float* c, const uint32_t* a, const uint32_t* b) {
    asm volatile("mma.sync.aligned.m16n8k16.row.col.f32.f16.f16.f32 "
        "{%0,%1,%2,%3}, {%4,%5,%6,%7}, {%8,%9}, {%0,%1,%2,%3};"
        : "+f"(c[0]), "+f"(c[1]), "+f"(c[2]), "+f"(c[3])
        : "r"(a[0]), "r"(a[1]), "r"(a[2]), "r"(a[3]), "r"(b[0]), "r"(b[1]));
}

// fast sin: 2-term Cody-Waite + MUFU (validated: rel_err contribution ~1e-6)
__device__ __forceinline__ float fast_sin(float x) {
    float k = rintf(x * 0.15915494309189535f);
    float r = fmaf(k, -6.2831854820251465f, x);
    r = fmaf(k, 1.7484556e-7f, r);
    return __sinf(r);
}

// X smem: row m = 512B (256 fp16), 16B chunk c swizzled c^(m&7)
__device__ __forceinline__ void store_x(char* sm, int m, int k, float x) {
    uint32_t c = (uint32_t)(k >> 3);
    uint32_t o = ((uint32_t)m << 9) + ((c ^ (uint32_t)(m & 7)) << 4) + (((uint32_t)k & 7u) << 1);
    *(__half*)(sm + X_OFF + o) = __float2half_rn(x);
}

// ---------- prep: fp16-round + transpose weights to g_B[lm][n][k] ----------
__global__ void prep_kernel(const float* __restrict__ Ws, const float* __restrict__ Wh) {
    int i = blockIdx.x * blockDim.x + threadIdx.x;
    if (i >= 8 * 65536) return;
    int lm = i >> 16;               // l*2 + mat
    int e  = i & 65535;             // k*256 + n
    int k = e >> 8, n = e & 255;
    const float* W = (lm & 1) ? Wh : Ws;
    g_B[(lm << 16) + (n << 8) + k] = __float2half_rn(W[(lm >> 1) * 65536 + e]);
}

// ---------- B chunk loader: [256n][32k] fp16 (16KB), 64B rows, swz cin^((n>>1)&3) ----------
__device__ __forceinline__ void load_b_chunk(uint32_t sb, int lm, int kc, int buf, int t) {
#pragma unroll
    for (int ii = 0; ii < 4; ii++) {
        int i = t + ii * THREADS;                 // 0..1023 16B units
        int n = i >> 2, cin = i & 3;
        const __half* g = g_B + (lm << 16) + (n << 8) + (kc << 5) + (cin << 3);
        uint32_t dst = sb + B_OFF + ((uint32_t)buf << 14)
                     + ((uint32_t)n << 6) + ((uint32_t)(cin ^ ((n >> 1) & 3)) << 4);
        asm volatile("cp.async.cg.shared.global [%0], [%1], 16;" :: "r"(dst), "l"(g));
    }
}

// ---------- fp16 GEMM: acc(32m x 64n per warp) = X @ W, K=256 in 8 chunks ----------
__device__ __forceinline__ void run_gemm(uint32_t sb, int lm, int t, int lane,
                                         int wm, int wn, float acc[2][8][4])
{
#pragma unroll
    for (int mt = 0; mt < 2; mt++)
#pragma unroll
        for (int nt = 0; nt < 8; nt++)
#pragma unroll
            for (int r = 0; r < 4; r++) acc[mt][nt][r] = 0.0f;

    const int arow = lane & 15;
    const int asel = lane >> 4;
    const int quad = lane >> 3, r8 = lane & 7;
    const int brow_off = ((quad >> 1) << 3) + r8;
    const int bsel = quad & 1;

    load_b_chunk(sb, lm, 0, 0, t);
    asm volatile("cp.async.commit_group;" ::: "memory");

    for (int kc = 0; kc < 8; kc++) {
        asm volatile("cp.async.wait_group 0;" ::: "memory");
        __syncthreads();                          // chunk ready; prev reads done
        if (kc < 7) {
            load_b_chunk(sb, lm, kc + 1, (kc + 1) & 1, t);
            asm volatile("cp.async.commit_group;" ::: "memory");
        }
        const uint32_t bbase = sb + B_OFF + ((uint32_t)(kc & 1) << 14);
#pragma unroll
        for (int ks = 0; ks < 2; ks++) {
            uint32_t ah[2][4];
            const int cidx = (kc << 2) + (ks << 1) + asel;   // global 16B k-chunk
#pragma unroll
            for (int mt = 0; mt < 2; mt++) {
                int row = wm * 32 + mt * 16 + arow;
                uint32_t off = ((uint32_t)row << 9) + ((uint32_t)(cidx ^ (row & 7)) << 4);
                ldsm4(ah[mt], sb + X_OFF + off);
            }
#pragma unroll
            for (int nt = 0; nt < 4; nt++) {
                uint32_t bh[4];
                int nrow = wn * 64 + nt * 16 + brow_off;
                int cin = (ks << 1) + bsel;
                uint32_t boff = ((uint32_t)nrow << 6)
                              + ((uint32_t)(cin ^ ((nrow >> 1) & 3)) << 4);
                ldsm4(bh, bbase + boff);
#pragma unroll
                for (int mt = 0; mt < 2; mt++) {
                    mma16816(acc[mt][nt * 2],     ah[mt], bh);
                    mma16816(acc[mt][nt * 2 + 1], ah[mt], bh + 2);
                }
            }
        }
    }
    __syncthreads();                              // all X/B reads done before epilogue writes
}

// ---------- main ----------
__global__ void __launch_bounds__(THREADS, 2)
ffb_main(const float* __restrict__ in_pos, const float* __restrict__ table,
         const float* __restrict__ ffn_A, const float* __restrict__ W0,
         const float* __restrict__ b0,    const float* __restrict__ bs,
         const float* __restrict__ bh,    float* __restrict__ out)
{
    extern __shared__ char sm[];
    const uint32_t sb = smem_u32(sm);
    const int t = threadIdx.x, w = t >> 5, lane = t & 31;
    const int wm = w & 1, wn = w >> 1;             // 2m x 4n warp grid
    const int base = blockIdx.x * MTILE;

    float* shpos = (float*)(sm + POS_OFF);
    float* shg   = (float*)(sm + SHG_OFF);
    float* shA   = (float*)(sm + SHA_OFF);
    float* shb   = (float*)(sm + SHB_OFF);

    if (t < 3 * MTILE) shpos[t] = in_pos[base * 3 + t];
    __syncthreads();

    // ---- hash-grid encode: 512 tasks = 64 pts x 8 corners (bit-exact, validated) ----
#pragma unroll
    for (int rep = 0; rep < 2; rep++) {
        int task = t + THREADS * rep;
        int m = task >> 3, c = task & 7;
        const unsigned ox = (c >> 2) & 1u, oy = (c >> 1) & 1u, oz = c & 1u;
        const float px = (shpos[3*m + 0] + 1.0f) * 0.5f;
        const float py = (shpos[3*m + 1] + 1.0f) * 0.5f;
        const float pz = (shpos[3*m + 2] + 1.0f) * 0.5f;
#pragma unroll
        for (int l = 0; l < 4; l++) {
            const float res = (float)(16 << l);
            float sx = px*res, sy = py*res, sz = pz*res;
            float fx = floorf(sx), fy = floorf(sy), fz = floorf(sz);
            float rx = sx-fx, ry = sy-fy, rz = sz-fz;
            unsigned ux = (unsigned)fx + ox, uy = (unsigned)fy + oy, uz = (unsigned)fz + oz;
            unsigned idx = (ux ^ (uy * 2654435761u) ^ (uz * 805459861u)) & 32767u;
            const float4* fp = (const float4*)(table + ((size_t)(l << 15) + idx) * 8);
            float4 f0 = __ldg(fp), f1 = __ldg(fp + 1);
            float wt = (ox ? rx : 1.0f-rx) * (oy ? ry : 1.0f-ry) * (oz ? rz : 1.0f-rz);
            float v[8] = { f0.x*wt, f0.y*wt, f0.z*wt, f0.w*wt,
                           f1.x*wt, f1.y*wt, f1.z*wt, f1.w*wt };
#pragma unroll
            for (int s = 1; s < 8; s <<= 1)
#pragma unroll
                for (int j = 0; j < 8; j++)
                    v[j] += __shfl_xor_sync(0xffffffffu, v[j], s);
            if (c == 0) {
                float* gp = shg + m * 32 + l * 8;
#pragma unroll
                for (int j = 0; j < 8; j++) gp[j] = v[j];
            }
        }
    }

    // ---- layer 0: X = sin(pos @ W0 + b0) -> fp16 smem ----
    {
        const int k = t;
        const float wx = __ldg(W0 + k), wy = __ldg(W0 + 256 + k),
                    wz = __ldg(W0 + 512 + k), bb = __ldg(b0 + k);
#pragma unroll 8
        for (int m = 0; m < MTILE; m++) {
            float a = fmaf(shpos[3*m], wx, fmaf(shpos[3*m+1], wy, fmaf(shpos[3*m+2], wz, bb)));
            store_x(sm, m, k, fast_sin(a));
        }
    }

    float acc[2][8][4];

#pragma unroll 1
    for (int l = 0; l < 4; l++) {
        __syncthreads();   // guard shA/shb overwrite vs prev layer's epilogue reads
        const float gsc = 6.2831853071795864f * (float)(1 << l);
#pragma unroll
        for (int i = t; i < 2048; i += THREADS) {
            int n = i >> 3, f = i & 7;
            shA[i] = __ldg(ffn_A + ((l * 8 + f) << 8) + n) * gsc;
        }
        shb[t]       = __ldg(bs + (l << 8) + t);
        shb[256 + t] = __ldg(bh + (l << 8) + t);
        // ordered before epilogue reads by run_gemm's internal __syncthreads

        // GEMM1: S = X @ Ws[l]
        run_gemm(sb, l * 2, t, lane, wm, wn, acc);

        // epilogue1: x = sin(S+bs) + sin(grid.A'); write new X (fp16)
#pragma unroll
        for (int mt = 0; mt < 2; mt++) {
#pragma unroll
            for (int h = 0; h < 2; h++) {
                const int m = wm * 32 + mt * 16 + (lane >> 2) + h * 8;
                const float* gp = shg + m * 32 + l * 8;
                float4 g0 = *(const float4*)gp, g1 = *(const float4*)(gp + 4);
#pragma unroll
                for (int nt = 0; nt < 8; nt++) {
                    const int n = wn * 64 + nt * 8 + (lane & 3) * 2;
#pragma unroll
                    for (int u = 0; u < 2; u++) {
                        float S = acc[mt][nt][h * 2 + u] + shb[n + u];
                        const float4 a0 = *(const float4*)(shA + (n + u) * 8);
                        const float4 a1 = *(const float4*)(shA + (n + u) * 8 + 4);
                        float g = g0.x * a0.x;
                        g = fmaf(g0.y, a0.y, g); g = fmaf(g0.z, a0.z, g);
                        g = fmaf(g0.w, a0.w, g); g = fmaf(g1.x, a1.x, g);
                        g = fmaf(g1.y, a1.y, g); g = fmaf(g1.z, a1.z, g);
                        g = fmaf(g1.w, a1.w, g);
                        store_x(sm, m, n + u, fast_sin(S) + fast_sin(g));
                    }
                }
            }
        }
        // GEMM2 reads of X ordered after these writes by its first __syncthreads

        // GEMM2: D = X @ Wh[l]
        run_gemm(sb, l * 2 + 1, t, lane, wm, wn, acc);

        // epilogue2: out[m][n] (+)= sin(D + bh)   (exclusive cell ownership)
#pragma unroll
        for (int mt = 0; mt < 2; mt++) {
#pragma unroll
            for (int h = 0; h < 2; h++) {
                const int m = wm * 32 + mt * 16 + (lane >> 2) + h * 8;
                float* op = out + (size_t)(base + m) * 256;
#pragma unroll
                for (int nt = 0; nt < 8; nt++) {
                    const int n = wn * 64 + nt * 8 + (lane & 3) * 2;
                    float v0 = fast_sin(acc[mt][nt][h * 2 + 0] + shb[256 + n]);
                    float v1 = fast_sin(acc[mt][nt][h * 2 + 1] + shb[256 + n + 1]);
                    float2* p = (float2*)(op + n);
                    if (l == 0) {
                        *p = make_float2(v0, v1);
                    } else {
                        float2 o = *p;
                        *p = make_float2(o.x + v0, o.y + v1);
                    }
                }
            }
        }
    }
}

extern "C" void kernel_launch(void* const* d_in, const int* in_sizes, int n_in,
                              void* d_out, int out_size)
{
    const float* in_pos = (const float*)d_in[0];
    const float* table  = (const float*)d_in[1];
    const float* ffn_A  = (const float*)d_in[2];
    const float* W0     = (const float*)d_in[3];
    const float* b0     = (const float*)d_in[4];
    const float* Ws     = (const float*)d_in[5];
    const float* bs     = (const float*)d_in[6];
    const float* Wh     = (const float*)d_in[7];
    const float* bh     = (const float*)d_in[8];
    float* out = (float*)d_out;

    cudaFuncSetAttribute(ffb_main, cudaFuncAttributeMaxDynamicSharedMemorySize, SMEM_BYTES);

    prep_kernel<<<(8 * 65536 + 255) / 256, 256>>>(Ws, Wh);
    ffb_main<<<NBLK, THREADS, SMEM_BYTES>>>(in_pos, table, ffn_A, W0, b0, bs, bh, out);
}